// round 13
// baseline (speedup 1.0000x reference)
#include <cuda_runtime.h>
#include <cuda_fp16.h>

// KNNInterpolate — L2-traffic-optimized 2-kernel pipeline.
//
// Gather pass is at ~94% of the LTS chip cap with compulsory traffic
// (192 MB fp16 gathers + 128 MB fp32 stores + 4 MB meta): floored.
// R12: prep becomes a single-wave persistent kernel; conversion (DRAM-bound)
// and weights (latency-bound) roles co-resident on every SM by block parity,
// overlapping in max() instead of sum().
//
// Inputs (metadata order):
//   d_in[0] s_feats          float32 [65536, 128]
//   d_in[1] q_points         float32 [262144, 3]
//   d_in[2] s_points         float32 [65536, 3]
//   d_in[3] neighbor_indices int32   [262144, 3]
// Output: float32 [262144, 128]

#define C_FEAT 128
#define N_SRC 65536
#define M_QRY 262144
#define EPS 1e-8f

// fp16 feature table: 65536 x 128 halfs = 16 MB, as uint4 for 16B stores.
#define FEATS_U4 (N_SRC * C_FEAT / 8)   // 1048576
__device__ uint4 g_feats_h[FEATS_U4];

// 16B metadata: x=i0, y=i1, z=i2, w=half2(w0,w1). w2 = 1-w0-w1.
__device__ int4 g_meta[M_QRY];

#define PREP_BLOCKS 1184   // 148 SMs x 8 co-resident 256-thread blocks
#define ROLE_BLOCKS (PREP_BLOCKS / 2)   // 592 per role

__device__ __forceinline__ float wgt3(const float* __restrict__ sp, int i,
                                      float qx, float qy, float qz)
{
    float dx = qx - __ldg(sp + 3ll * i + 0);
    float dy = qy - __ldg(sp + 3ll * i + 1);
    float dz = qz - __ldg(sp + 3ll * i + 2);
    return 1.0f / (dx * dx + dy * dy + dz * dz + EPS);
}

__device__ __forceinline__ unsigned pack_h2(float a, float b)
{
    __half2 h = __floats2half2_rn(a, b);
    return *reinterpret_cast<unsigned*>(&h);
}

// Single-wave persistent prep: even blocks convert, odd blocks do weights.
__global__ __launch_bounds__(256) void prep_kernel(
    const float* __restrict__ s_feats,
    const float* __restrict__ q_points,
    const float* __restrict__ s_points,
    const int* __restrict__ nidx,
    int M)
{
    const int role_blk = blockIdx.x >> 1;
    const int stride = ROLE_BLOCKS * 256;

    if ((blockIdx.x & 1) == 0) {
        // ---- conversion: grid-stride over uint4 records (coalesced) ----
        const float4* src = (const float4*)s_feats;
        for (int r = role_blk * 256 + threadIdx.x; r < FEATS_U4; r += stride) {
            const float4 f0 = __ldcs(src + 2ll * r);   // read-once
            const float4 f1 = __ldcs(src + 2ll * r + 1);
            uint4 p;
            p.x = pack_h2(f0.x, f0.y);
            p.y = pack_h2(f0.z, f0.w);
            p.z = pack_h2(f1.x, f1.y);
            p.w = pack_h2(f1.z, f1.w);
            g_feats_h[r] = p;                          // stays in L2
        }
    } else {
        // ---- weights: grid-stride, one query per thread-iteration ----
        for (int m = role_blk * 256 + threadIdx.x; m < M; m += stride) {
            const int i0 = __ldg(nidx + 3ll * m + 0);
            const int i1 = __ldg(nidx + 3ll * m + 1);
            const int i2 = __ldg(nidx + 3ll * m + 2);

            const float qx = __ldg(q_points + 3ll * m + 0);
            const float qy = __ldg(q_points + 3ll * m + 1);
            const float qz = __ldg(q_points + 3ll * m + 2);

            float w0 = wgt3(s_points, i0, qx, qy, qz);
            float w1 = wgt3(s_points, i1, qx, qy, qz);
            float w2 = wgt3(s_points, i2, qx, qy, qz);
            const float s = 1.0f / (w0 + w1 + w2);

            int4 mv;
            mv.x = i0;
            mv.y = i1;
            mv.z = i2;
            mv.w = (int)pack_h2(w0 * s, w1 * s);
            g_meta[m] = mv;
        }
    }
}

// Weighted sum of three fp16 4-channel chunks (fp32 accumulate).
__device__ __forceinline__ float4 wsum_h(uint2 ga, uint2 gb, uint2 gc,
                                         float w0, float w1, float w2)
{
    const float2 a01 = __half22float2(*reinterpret_cast<__half2*>(&ga.x));
    const float2 a23 = __half22float2(*reinterpret_cast<__half2*>(&ga.y));
    const float2 b01 = __half22float2(*reinterpret_cast<__half2*>(&gb.x));
    const float2 b23 = __half22float2(*reinterpret_cast<__half2*>(&gb.y));
    const float2 c01 = __half22float2(*reinterpret_cast<__half2*>(&gc.x));
    const float2 c23 = __half22float2(*reinterpret_cast<__half2*>(&gc.y));
    float4 r;
    r.x = w0 * a01.x; r.y = w0 * a01.y; r.z = w0 * a23.x; r.w = w0 * a23.y;
    r.x = fmaf(w1, b01.x, r.x); r.y = fmaf(w1, b01.y, r.y);
    r.z = fmaf(w1, b23.x, r.z); r.w = fmaf(w1, b23.y, r.w);
    r.x = fmaf(w2, c01.x, r.x); r.y = fmaf(w2, c01.y, r.y);
    r.z = fmaf(w2, c23.x, r.z); r.w = fmaf(w2, c23.y, r.w);
    return r;
}

// One warp per TWO queries; each lane owns 4 channels (8B fp16 per gather).
__global__ __launch_bounds__(256) void gather_kernel(
    float4* __restrict__ out,
    int n_pairs)
{
    const int pair = (int)((blockIdx.x * blockDim.x + threadIdx.x) >> 5);
    const int lane = threadIdx.x & 31;
    if (pair >= n_pairs) return;

    const int m0 = 2 * pair;

    // 16B meta per query, read-once -> evict-first
    const int4 mv0 = __ldcs(&g_meta[m0]);
    const int4 mv1 = __ldcs(&g_meta[m0 + 1]);

    unsigned pw0 = (unsigned)mv0.w;
    unsigned pw1 = (unsigned)mv1.w;
    const float2 w01a = __half22float2(*reinterpret_cast<__half2*>(&pw0));
    const float2 w01b = __half22float2(*reinterpret_cast<__half2*>(&pw1));
    const float w2a = 1.0f - w01a.x - w01a.y;
    const float w2b = 1.0f - w01b.x - w01b.y;

    // fp16 row = 32 uint2 (256B); lane's chunk = uint2 at [row*32 + lane]
    const uint2* sfl = (const uint2*)g_feats_h + lane;

    const uint2 a0 = __ldg(sfl + 32ll * mv0.x);
    const uint2 b0 = __ldg(sfl + 32ll * mv0.y);
    const uint2 c0 = __ldg(sfl + 32ll * mv0.z);
    const uint2 a1 = __ldg(sfl + 32ll * mv1.x);
    const uint2 b1 = __ldg(sfl + 32ll * mv1.y);
    const uint2 c1 = __ldg(sfl + 32ll * mv1.z);

    float4* o = out + (long long)m0 * (C_FEAT / 4) + lane;
    __stcs(o, wsum_h(a0, b0, c0, w01a.x, w01a.y, w2a));
    __stcs(o + (C_FEAT / 4), wsum_h(a1, b1, c1, w01b.x, w01b.y, w2b));
}

extern "C" void kernel_launch(void* const* d_in, const int* in_sizes, int n_in,
                              void* d_out, int out_size)
{
    const float* s_feats = (const float*)d_in[0];
    const float* q_points = (const float*)d_in[1];
    const float* s_points = (const float*)d_in[2];
    const int* nidx = (const int*)d_in[3];
    float4* out = (float4*)d_out;

    const int M = in_sizes[1] / 3;   // 262144
    const int n_pairs = M / 2;

    prep_kernel<<<PREP_BLOCKS, 256>>>(s_feats, q_points, s_points, nidx, M);

    const int warps_per_block = 8;   // 256 threads
    const int blocks = (n_pairs + warps_per_block - 1) / warps_per_block;
    gather_kernel<<<blocks, warps_per_block * 32>>>(out, n_pairs);
}

// round 14
// speedup vs baseline: 1.0152x; 1.0152x over previous
#include <cuda_runtime.h>
#include <cuda_fp16.h>

// KNNInterpolate — L2-traffic-optimized 2-kernel pipeline.
//
// Gather pass: at ~94% of the LTS chip cap with compulsory traffic
// (192 MB fp16 gathers + 128 MB fp32 stores + 4 MB meta) — floored, unchanged.
// R13 prep: single-wave kernel with WARP-level role split (per-SM co-residency
// of the DRAM-bound conversion stream and the latency-bound weights role) and
// batch-8 unrolled conversion to keep per-thread MLP high (R12's mistake).
//
// Inputs (metadata order):
//   d_in[0] s_feats          float32 [65536, 128]
//   d_in[1] q_points         float32 [262144, 3]
//   d_in[2] s_points         float32 [65536, 3]
//   d_in[3] neighbor_indices int32   [262144, 3]
// Output: float32 [262144, 128]

#define C_FEAT 128
#define N_SRC 65536
#define M_QRY 262144
#define EPS 1e-8f

// fp16 feature table: 65536 x 128 halfs = 16 MB, as uint4 for 16B stores.
#define FEATS_U4 (N_SRC * C_FEAT / 8)   // 1048576
__device__ uint4 g_feats_h[FEATS_U4];

// 16B metadata: x=i0, y=i1, z=i2, w=half2(w0,w1). w2 = 1-w0-w1.
__device__ int4 g_meta[M_QRY];

#define PREP_BLOCKS 1184                  // 148 SMs x 8 co-resident blocks
#define CONV_LANES (PREP_BLOCKS * 128)    // warps 0-3 of each block: 151552
#define WGT_LANES  (PREP_BLOCKS * 128)    // warps 4-7 of each block: 151552
#define CONV_ITERS 8                      // ceil(1048576 / 151552) = 7 -> 8 w/ guard
#define WGT_ITERS  2                      // ceil(262144  / 151552) = 2

__device__ __forceinline__ float wgt3(const float* __restrict__ sp, int i,
                                      float qx, float qy, float qz)
{
    float dx = qx - __ldg(sp + 3ll * i + 0);
    float dy = qy - __ldg(sp + 3ll * i + 1);
    float dz = qz - __ldg(sp + 3ll * i + 2);
    return 1.0f / (dx * dx + dy * dy + dz * dz + EPS);
}

__device__ __forceinline__ unsigned pack_h2(float a, float b)
{
    __half2 h = __floats2half2_rn(a, b);
    return *reinterpret_cast<unsigned*>(&h);
}

// Single-wave prep, warp-level role split inside every block.
__global__ __launch_bounds__(256) void prep_kernel(
    const float* __restrict__ s_feats,
    const float* __restrict__ q_points,
    const float* __restrict__ s_points,
    const int* __restrict__ nidx,
    int M)
{
    const int wid = threadIdx.x >> 5;          // 0..7
    const int sub = (threadIdx.x & 127);       // id within the 4-warp role group

    if (wid < 4) {
        // ---- conversion: batch-8 independent coalesced records ----
        const int cid = blockIdx.x * 128 + sub;
        const float4* src = (const float4*)s_feats;
        #pragma unroll
        for (int k = 0; k < CONV_ITERS; k++) {
            const long long r = cid + (long long)k * CONV_LANES;
            if (r < FEATS_U4) {
                const float4 f0 = __ldcs(src + 2 * r);   // read-once
                const float4 f1 = __ldcs(src + 2 * r + 1);
                uint4 p;
                p.x = pack_h2(f0.x, f0.y);
                p.y = pack_h2(f0.z, f0.w);
                p.z = pack_h2(f1.x, f1.y);
                p.w = pack_h2(f1.z, f1.w);
                g_feats_h[r] = p;                        // stays in L2
            }
        }
    } else {
        // ---- weights: 2 queries per thread ----
        const int tid = blockIdx.x * 128 + sub;
        #pragma unroll
        for (int k = 0; k < WGT_ITERS; k++) {
            const int m = tid + k * WGT_LANES;
            if (m < M) {
                const int i0 = __ldg(nidx + 3ll * m + 0);
                const int i1 = __ldg(nidx + 3ll * m + 1);
                const int i2 = __ldg(nidx + 3ll * m + 2);

                const float qx = __ldg(q_points + 3ll * m + 0);
                const float qy = __ldg(q_points + 3ll * m + 1);
                const float qz = __ldg(q_points + 3ll * m + 2);

                float w0 = wgt3(s_points, i0, qx, qy, qz);
                float w1 = wgt3(s_points, i1, qx, qy, qz);
                float w2 = wgt3(s_points, i2, qx, qy, qz);
                const float s = 1.0f / (w0 + w1 + w2);

                int4 mv;
                mv.x = i0;
                mv.y = i1;
                mv.z = i2;
                mv.w = (int)pack_h2(w0 * s, w1 * s);
                g_meta[m] = mv;
            }
        }
    }
}

// Weighted sum of three fp16 4-channel chunks (fp32 accumulate).
__device__ __forceinline__ float4 wsum_h(uint2 ga, uint2 gb, uint2 gc,
                                         float w0, float w1, float w2)
{
    const float2 a01 = __half22float2(*reinterpret_cast<__half2*>(&ga.x));
    const float2 a23 = __half22float2(*reinterpret_cast<__half2*>(&ga.y));
    const float2 b01 = __half22float2(*reinterpret_cast<__half2*>(&gb.x));
    const float2 b23 = __half22float2(*reinterpret_cast<__half2*>(&gb.y));
    const float2 c01 = __half22float2(*reinterpret_cast<__half2*>(&gc.x));
    const float2 c23 = __half22float2(*reinterpret_cast<__half2*>(&gc.y));
    float4 r;
    r.x = w0 * a01.x; r.y = w0 * a01.y; r.z = w0 * a23.x; r.w = w0 * a23.y;
    r.x = fmaf(w1, b01.x, r.x); r.y = fmaf(w1, b01.y, r.y);
    r.z = fmaf(w1, b23.x, r.z); r.w = fmaf(w1, b23.y, r.w);
    r.x = fmaf(w2, c01.x, r.x); r.y = fmaf(w2, c01.y, r.y);
    r.z = fmaf(w2, c23.x, r.z); r.w = fmaf(w2, c23.y, r.w);
    return r;
}

// One warp per TWO queries; each lane owns 4 channels (8B fp16 per gather).
__global__ __launch_bounds__(256) void gather_kernel(
    float4* __restrict__ out,
    int n_pairs)
{
    const int pair = (int)((blockIdx.x * blockDim.x + threadIdx.x) >> 5);
    const int lane = threadIdx.x & 31;
    if (pair >= n_pairs) return;

    const int m0 = 2 * pair;

    // 16B meta per query, read-once -> evict-first
    const int4 mv0 = __ldcs(&g_meta[m0]);
    const int4 mv1 = __ldcs(&g_meta[m0 + 1]);

    unsigned pw0 = (unsigned)mv0.w;
    unsigned pw1 = (unsigned)mv1.w;
    const float2 w01a = __half22float2(*reinterpret_cast<__half2*>(&pw0));
    const float2 w01b = __half22float2(*reinterpret_cast<__half2*>(&pw1));
    const float w2a = 1.0f - w01a.x - w01a.y;
    const float w2b = 1.0f - w01b.x - w01b.y;

    // fp16 row = 32 uint2 (256B); lane's chunk = uint2 at [row*32 + lane]
    const uint2* sfl = (const uint2*)g_feats_h + lane;

    const uint2 a0 = __ldg(sfl + 32ll * mv0.x);
    const uint2 b0 = __ldg(sfl + 32ll * mv0.y);
    const uint2 c0 = __ldg(sfl + 32ll * mv0.z);
    const uint2 a1 = __ldg(sfl + 32ll * mv1.x);
    const uint2 b1 = __ldg(sfl + 32ll * mv1.y);
    const uint2 c1 = __ldg(sfl + 32ll * mv1.z);

    float4* o = out + (long long)m0 * (C_FEAT / 4) + lane;
    __stcs(o, wsum_h(a0, b0, c0, w01a.x, w01a.y, w2a));
    __stcs(o + (C_FEAT / 4), wsum_h(a1, b1, c1, w01b.x, w01b.y, w2b));
}

extern "C" void kernel_launch(void* const* d_in, const int* in_sizes, int n_in,
                              void* d_out, int out_size)
{
    const float* s_feats = (const float*)d_in[0];
    const float* q_points = (const float*)d_in[1];
    const float* s_points = (const float*)d_in[2];
    const int* nidx = (const int*)d_in[3];
    float4* out = (float4*)d_out;

    const int M = in_sizes[1] / 3;   // 262144
    const int n_pairs = M / 2;

    prep_kernel<<<PREP_BLOCKS, 256>>>(s_feats, q_points, s_points, nidx, M);

    const int warps_per_block = 8;   // 256 threads
    const int blocks = (n_pairs + warps_per_block - 1) / warps_per_block;
    gather_kernel<<<blocks, warps_per_block * 32>>>(out, n_pairs);
}

// round 15
// speedup vs baseline: 1.0410x; 1.0254x over previous
#include <cuda_runtime.h>
#include <cuda_fp16.h>

// KNNInterpolate — L2-traffic-optimized 2-kernel pipeline.
//
// Gather pass: at ~94% of the LTS chip cap with compulsory traffic
// (192 MB fp16 gathers + 128 MB fp32 stores + 4 MB meta) — floored, unchanged.
// R14 prep: ONE kernel, 1024 blocks (single wave, <=32 regs), each thread
// converts 4 full-MLP records THEN computes 1 query's weights in the same
// thread. Conversion keeps R11's exact shape (no lane loss — R12/R13's
// mistake); the weights tail overlaps in-flight conversion instead of running
// as a serial second wave.
//
// Inputs (metadata order):
//   d_in[0] s_feats          float32 [65536, 128]
//   d_in[1] q_points         float32 [262144, 3]
//   d_in[2] s_points         float32 [65536, 3]
//   d_in[3] neighbor_indices int32   [262144, 3]
// Output: float32 [262144, 128]

#define C_FEAT 128
#define N_SRC 65536
#define M_QRY 262144
#define EPS 1e-8f

// fp16 feature table: 65536 x 128 halfs = 16 MB, as uint4 for 16B stores.
#define FEATS_U4 (N_SRC * C_FEAT / 8)   // 1048576
__device__ uint4 g_feats_h[FEATS_U4];

// 16B metadata: x=i0, y=i1, z=i2, w=half2(w0,w1). w2 = 1-w0-w1.
__device__ int4 g_meta[M_QRY];

#define PREP_THREADS M_QRY                    // 262144 = 1024 blocks x 256
#define CONV_PER_THREAD (FEATS_U4 / PREP_THREADS)   // 4

__device__ __forceinline__ float wgt3(const float* __restrict__ sp, int i,
                                      float qx, float qy, float qz)
{
    float dx = qx - __ldg(sp + 3ll * i + 0);
    float dy = qy - __ldg(sp + 3ll * i + 1);
    float dz = qz - __ldg(sp + 3ll * i + 2);
    return 1.0f / (dx * dx + dy * dy + dz * dz + EPS);
}

__device__ __forceinline__ unsigned pack_h2(float a, float b)
{
    __half2 h = __floats2half2_rn(a, b);
    return *reinterpret_cast<unsigned*>(&h);
}

// Single-wave fused prep: conversion burst, then this thread's query weights.
__global__ __launch_bounds__(256, 8) void prep_kernel(
    const float* __restrict__ s_feats,
    const float* __restrict__ q_points,
    const float* __restrict__ s_points,
    const int* __restrict__ nidx)
{
    const int t = blockIdx.x * 256 + threadIdx.x;   // 0..262143

    // ---- conversion: 4 independent coalesced 16B records (8 LDG.128) ----
    {
        const float4* src = (const float4*)s_feats;
        #pragma unroll
        for (int k = 0; k < CONV_PER_THREAD; k++) {
            const long long r = t + (long long)k * PREP_THREADS;
            const float4 f0 = __ldcs(src + 2 * r);   // read-once
            const float4 f1 = __ldcs(src + 2 * r + 1);
            uint4 p;
            p.x = pack_h2(f0.x, f0.y);
            p.y = pack_h2(f0.z, f0.w);
            p.z = pack_h2(f1.x, f1.y);
            p.w = pack_h2(f1.z, f1.w);
            g_feats_h[r] = p;                        // stays in L2
        }
    }

    // ---- weights: one query per thread (m == t) ----
    {
        const int m = t;
        const int i0 = __ldg(nidx + 3ll * m + 0);
        const int i1 = __ldg(nidx + 3ll * m + 1);
        const int i2 = __ldg(nidx + 3ll * m + 2);

        const float qx = __ldg(q_points + 3ll * m + 0);
        const float qy = __ldg(q_points + 3ll * m + 1);
        const float qz = __ldg(q_points + 3ll * m + 2);

        float w0 = wgt3(s_points, i0, qx, qy, qz);
        float w1 = wgt3(s_points, i1, qx, qy, qz);
        float w2 = wgt3(s_points, i2, qx, qy, qz);
        const float s = 1.0f / (w0 + w1 + w2);

        int4 mv;
        mv.x = i0;
        mv.y = i1;
        mv.z = i2;
        mv.w = (int)pack_h2(w0 * s, w1 * s);
        g_meta[m] = mv;
    }
}

// Weighted sum of three fp16 4-channel chunks (fp32 accumulate).
__device__ __forceinline__ float4 wsum_h(uint2 ga, uint2 gb, uint2 gc,
                                         float w0, float w1, float w2)
{
    const float2 a01 = __half22float2(*reinterpret_cast<__half2*>(&ga.x));
    const float2 a23 = __half22float2(*reinterpret_cast<__half2*>(&ga.y));
    const float2 b01 = __half22float2(*reinterpret_cast<__half2*>(&gb.x));
    const float2 b23 = __half22float2(*reinterpret_cast<__half2*>(&gb.y));
    const float2 c01 = __half22float2(*reinterpret_cast<__half2*>(&gc.x));
    const float2 c23 = __half22float2(*reinterpret_cast<__half2*>(&gc.y));
    float4 r;
    r.x = w0 * a01.x; r.y = w0 * a01.y; r.z = w0 * a23.x; r.w = w0 * a23.y;
    r.x = fmaf(w1, b01.x, r.x); r.y = fmaf(w1, b01.y, r.y);
    r.z = fmaf(w1, b23.x, r.z); r.w = fmaf(w1, b23.y, r.w);
    r.x = fmaf(w2, c01.x, r.x); r.y = fmaf(w2, c01.y, r.y);
    r.z = fmaf(w2, c23.x, r.z); r.w = fmaf(w2, c23.y, r.w);
    return r;
}

// One warp per TWO queries; each lane owns 4 channels (8B fp16 per gather).
__global__ __launch_bounds__(256) void gather_kernel(
    float4* __restrict__ out,
    int n_pairs)
{
    const int pair = (int)((blockIdx.x * blockDim.x + threadIdx.x) >> 5);
    const int lane = threadIdx.x & 31;
    if (pair >= n_pairs) return;

    const int m0 = 2 * pair;

    // 16B meta per query, read-once -> evict-first
    const int4 mv0 = __ldcs(&g_meta[m0]);
    const int4 mv1 = __ldcs(&g_meta[m0 + 1]);

    unsigned pw0 = (unsigned)mv0.w;
    unsigned pw1 = (unsigned)mv1.w;
    const float2 w01a = __half22float2(*reinterpret_cast<__half2*>(&pw0));
    const float2 w01b = __half22float2(*reinterpret_cast<__half2*>(&pw1));
    const float w2a = 1.0f - w01a.x - w01a.y;
    const float w2b = 1.0f - w01b.x - w01b.y;

    // fp16 row = 32 uint2 (256B); lane's chunk = uint2 at [row*32 + lane]
    const uint2* sfl = (const uint2*)g_feats_h + lane;

    const uint2 a0 = __ldg(sfl + 32ll * mv0.x);
    const uint2 b0 = __ldg(sfl + 32ll * mv0.y);
    const uint2 c0 = __ldg(sfl + 32ll * mv0.z);
    const uint2 a1 = __ldg(sfl + 32ll * mv1.x);
    const uint2 b1 = __ldg(sfl + 32ll * mv1.y);
    const uint2 c1 = __ldg(sfl + 32ll * mv1.z);

    float4* o = out + (long long)m0 * (C_FEAT / 4) + lane;
    __stcs(o, wsum_h(a0, b0, c0, w01a.x, w01a.y, w2a));
    __stcs(o + (C_FEAT / 4), wsum_h(a1, b1, c1, w01b.x, w01b.y, w2b));
}

extern "C" void kernel_launch(void* const* d_in, const int* in_sizes, int n_in,
                              void* d_out, int out_size)
{
    const float* s_feats = (const float*)d_in[0];
    const float* q_points = (const float*)d_in[1];
    const float* s_points = (const float*)d_in[2];
    const int* nidx = (const int*)d_in[3];
    float4* out = (float4*)d_out;

    const int M = in_sizes[1] / 3;   // 262144
    const int n_pairs = M / 2;

    prep_kernel<<<PREP_THREADS / 256, 256>>>(s_feats, q_points, s_points, nidx);

    const int warps_per_block = 8;   // 256 threads
    const int blocks = (n_pairs + warps_per_block - 1) / warps_per_block;
    gather_kernel<<<blocks, warps_per_block * 32>>>(out, n_pairs);
}